// round 5
// baseline (speedup 1.0000x reference)
#include <cuda_runtime.h>
#include <math.h>
#include <stdint.h>

#define BN 8
#define C 256
#define HWn 4096
#define KFULL 2304

// ---------------- scratch (device globals: allocation-free) ----------------
__device__ float g_xt [(size_t)BN*HWn*C];        // x NHWC [b][pix][c]
__device__ float g_y1h[(size_t)BN*HWn*C];        // conv1 out NHWC (post BN+ReLU in place)
__device__ float g_d2 [(size_t)BN*C*HWn];        // deform conv raw, NCHW
__device__ float g_res[(size_t)BN*C*HWn];        // 1x1 shortcut raw, NCHW
__device__ float g_off[BN*18*HWn];
__device__ float g_mask[BN*9*HWn];
__device__ float g_col[(size_t)BN*HWn*KFULL];    // [b][pix][p*256+ci]
__device__ float g_stats[6*256];
__device__ float g_w1p[256*KFULL];               // w1 permuted  [co][t*256+ci]
__device__ float g_wdp[256*KFULL];               // w_d permuted [co][t*256+ci]
__device__ float g_wop[27*KFULL];                // off+mod packed+permuted
__device__ float g_bp[32];
__device__ float g_part[2*128*256];              // NHWC bn stage-1 partials

// ---------------- helpers -----------------------------------------------------
__device__ __forceinline__ unsigned f2tf(float v) {
    unsigned u; asm("cvt.rna.tf32.f32 %0, %1;" : "=r"(u) : "f"(v)); return u;
}
__device__ __forceinline__ void mma8(float* d, const uint4& a, const uint2& b) {
    asm volatile("mma.sync.aligned.m16n8k8.row.col.f32.tf32.tf32.f32 "
        "{%0,%1,%2,%3}, {%4,%5,%6,%7}, {%8,%9}, {%0,%1,%2,%3};"
        : "+f"(d[0]), "+f"(d[1]), "+f"(d[2]), "+f"(d[3])
        : "r"(a.x), "r"(a.y), "r"(a.z), "r"(a.w), "r"(b.x), "r"(b.y));
}

// ---------------- unified tf32 GEMM, fragment-resident smem -------------------
// D[64co x 128pix] = A[co][k] * B[k][pix], K chunks of 32, block = 128 thr.
// CONVB: B = implicit 3x3 im2col of NHWC tensor (k = t*256+ci).
// else:  B[k][pix] = Bm[((b*4096+pix)*ROWLEN) + k]  (k-contiguous rows).
// EPI 0: NCHW out + bias.  EPI 1: NHWC out + bias.  EPI 2: offsets/mask.
template<bool CONVB, int EPI>
__global__ __launch_bounds__(128) void gemm_v2(
    const float* __restrict__ A, const float* __restrict__ Bm,
    const float* __restrict__ bias,
    float* __restrict__ out0, float* __restrict__ out1,
    int Kdim, int AREAL, int ROWLEN)
{
    __shared__ uint4 sA4[4*4*32];     // [k8][m16 tile][lane] -> {a0,a1,a2,a3}
    __shared__ uint2 sB2[4*16*32];    // [k8][n8 tile][lane]  -> {b0,b1}
    __shared__ float sE[4352];

    const int tid = threadIdx.x, lane = tid & 31, warp = tid >> 5;
    const int wm = warp >> 1, wn = warp & 1;      // warp tile: 32co x 64pix
    const int pix0 = blockIdx.x * 128, co0 = blockIdx.y * 64, b = blockIdx.z;
    uint32_t* sA32 = (uint32_t*)sA4;
    uint32_t* sB32 = (uint32_t*)sB2;

    float acc0[8][4] = {}, acc1[8][4] = {};

    const int nch = Kdim >> 5;
    for (int ic = 0; ic < nch; ic++) {
        const int k0 = ic << 5;
        // ---- stage A: 64co x 32k into fragment layout ----
        #pragma unroll
        for (int i = 0; i < 4; i++) {
            int idx = tid + i*128;
            int co = idx >> 3, kq = idx & 7;      // k = kq*4 + j
            float4 v = make_float4(0.f, 0.f, 0.f, 0.f);
            if (co < AREAL)
                v = *(const float4*)(A + (size_t)(co0+co)*Kdim + k0 + kq*4);
            float vv[4] = {v.x, v.y, v.z, v.w};
            // slot32 = ((ks*4+mt)*32 + lane)*4 + reg ; ks=kq>>1, mt=co>>4,
            // lane=(co&7)*4+j, reg=(kq&1)*2 + ((co>>3)&1)
            const int base32 = ((kq>>1)*4 + (co>>4))*128 + (co&7)*16
                             + (kq&1)*2 + ((co>>3)&1);
            #pragma unroll
            for (int j0 = 0; j0 < 4; j0++) {
                int j = (j0 + tid) & 3;
                sA32[base32 + j*4] = f2tf(vv[j]);
            }
        }
        // ---- stage B: 32k x 128pix into fragment layout ----
        int ty = 0, tx = 0, ci0 = 0;
        if (CONVB) { int t = k0 >> 8; ty = t/3 - 1; tx = t%3 - 1; ci0 = k0 & 255; }
        #pragma unroll
        for (int i = 0; i < 8; i++) {
            int idx = tid + i*128;
            int pp = idx >> 3, kq = idx & 7;
            float4 v;
            if (CONVB) {
                int pix = pix0 + pp;
                int py = (pix>>6) + ty, px = (pix&63) + tx;
                if (py >= 0 && py < 64 && px >= 0 && px < 64)
                    v = *(const float4*)(Bm + ((size_t)b*4096 + py*64+px)*256 + ci0 + kq*4);
                else v = make_float4(0.f, 0.f, 0.f, 0.f);
            } else {
                v = *(const float4*)(Bm + ((size_t)b*4096 + pix0+pp)*(size_t)ROWLEN + k0 + kq*4);
            }
            float vv[4] = {v.x, v.y, v.z, v.w};
            // slot32 = ((ks*16+nt)*32 + lane)*2 + reg ; nt=pp>>3,
            // lane=(pp&7)*4+j, reg=kq&1
            const int base32 = ((kq>>1)*16 + (pp>>3))*64 + (pp&7)*8 + (kq&1);
            #pragma unroll
            for (int j0 = 0; j0 < 4; j0++) {
                int j = (j0 + tid) & 3;
                sB32[base32 + j*2] = f2tf(vv[j]);
            }
        }
        __syncthreads();
        // ---- mma: per warp 2 m16-tiles x 8 n8-tiles ----
        #pragma unroll
        for (int k8 = 0; k8 < 4; k8++) {
            uint4 a0 = sA4[(k8*4 + wm*2 + 0)*32 + lane];
            uint4 a1 = sA4[(k8*4 + wm*2 + 1)*32 + lane];
            #pragma unroll
            for (int nn = 0; nn < 8; nn++) {
                uint2 bb = sB2[(k8*16 + wn*8 + nn)*32 + lane];
                mma8(acc0[nn], a0, bb);
                mma8(acc1[nn], a1, bb);
            }
        }
        __syncthreads();
    }

    const int g = lane >> 2, tig = lane & 3;

    if (EPI == 0) {                       // ---- NCHW out, 2 passes over co halves
        #pragma unroll
        for (int pass = 0; pass < 2; pass++) {
            if (wm == pass) {
                #pragma unroll
                for (int m = 0; m < 2; m++) {
                    float (*ac)[4] = (m == 0) ? acc0 : acc1;
                    int r = m*16 + g;
                    #pragma unroll
                    for (int nn = 0; nn < 8; nn++) {
                        int pl = wn*64 + nn*8 + tig*2;
                        sE[r*132 + pl]       = ac[nn][0];
                        sE[r*132 + pl+1]     = ac[nn][1];
                        sE[(r+8)*132 + pl]   = ac[nn][2];
                        sE[(r+8)*132 + pl+1] = ac[nn][3];
                    }
                }
            }
            __syncthreads();
            #pragma unroll
            for (int i = 0; i < 8; i++) {
                int idx = tid + i*128;
                int r = idx >> 5, p4 = idx & 31;
                float4 v = *(float4*)&sE[r*132 + p4*4];
                int co = co0 + pass*32 + r;
                float bb = bias[co];
                v.x += bb; v.y += bb; v.z += bb; v.w += bb;
                *(float4*)(out0 + (((size_t)b*256 + co) << 12) + pix0 + p4*4) = v;
            }
            __syncthreads();
        }
    } else if (EPI == 1) {                // ---- NHWC out, 2 passes over pix halves
        #pragma unroll
        for (int pass = 0; pass < 2; pass++) {
            if (wn == pass) {
                #pragma unroll
                for (int m = 0; m < 2; m++) {
                    float (*ac)[4] = (m == 0) ? acc0 : acc1;
                    int r = wm*32 + m*16 + g;
                    #pragma unroll
                    for (int nn = 0; nn < 8; nn++) {
                        int pl = nn*8 + tig*2;
                        sE[pl*68 + r]       = ac[nn][0];
                        sE[(pl+1)*68 + r]   = ac[nn][1];
                        sE[pl*68 + r+8]     = ac[nn][2];
                        sE[(pl+1)*68 + r+8] = ac[nn][3];
                    }
                }
            }
            __syncthreads();
            #pragma unroll
            for (int i = 0; i < 8; i++) {
                int idx = tid + i*128;
                int pp = idx >> 4, c4 = idx & 15;
                float4 v = *(float4*)&sE[pp*68 + c4*4];
                const float4 bb = *(const float4*)(bias + co0 + c4*4);
                v.x += bb.x; v.y += bb.y; v.z += bb.z; v.w += bb.w;
                *(float4*)(out0 + ((size_t)b*4096 + pix0 + pass*64 + pp)*256 + co0 + c4*4) = v;
            }
            __syncthreads();
        }
    } else {                              // ---- EPI 2: offsets + mask
        if (wm == 0) {
            #pragma unroll
            for (int m = 0; m < 2; m++) {
                float (*ac)[4] = (m == 0) ? acc0 : acc1;
                int r = m*16 + g;
                #pragma unroll
                for (int nn = 0; nn < 8; nn++) {
                    int pl = wn*64 + nn*8 + tig*2;
                    sE[r*132 + pl]       = ac[nn][0];
                    sE[r*132 + pl+1]     = ac[nn][1];
                    sE[(r+8)*132 + pl]   = ac[nn][2];
                    sE[(r+8)*132 + pl+1] = ac[nn][3];
                }
            }
        }
        __syncthreads();
        #pragma unroll
        for (int r = 0; r < 27; r++) {
            float v = sE[r*132 + tid] + bias[r];
            int pix = pix0 + tid;
            if (r < 18) out0[((size_t)b*18 + r)*4096 + pix] = v;
            else        out1[((size_t)b*9 + r - 18)*4096 + pix] = 2.f/(1.f + expf(-v));
        }
    }
}

// ---------------- weight permute: out[co][t*256+ci] = in[co][ci*9+t] ---------
__global__ __launch_bounds__(256) void permuteK(const float* __restrict__ in,
                                                float* __restrict__ out)
{
    int i = blockIdx.x*256 + threadIdx.x;
    int co = i / KFULL, r = i - co*KFULL;
    int t = r >> 8, ci = r & 255;
    out[i] = in[co*KFULL + ci*9 + t];
}

__global__ __launch_bounds__(256) void pack_offmod(
    const float* __restrict__ w_off, const float* __restrict__ w_mod,
    const float* __restrict__ b_off, const float* __restrict__ b_mod,
    float* __restrict__ wp, float* __restrict__ bp)
{
    int i = blockIdx.x*256 + threadIdx.x;
    if (i < 27*KFULL) {
        int o = i / KFULL, r = i - o*KFULL;
        int t = r >> 8, ci = r & 255;
        wp[i] = (o < 18) ? w_off[o*KFULL + ci*9 + t] : w_mod[(o-18)*KFULL + ci*9 + t];
    }
    if (i < 27) bp[i] = (i < 18) ? b_off[i] : b_mod[i-18];
}

// ---------------- NCHW -> NHWC transpose (32x32 tiles) ------------------------
__global__ __launch_bounds__(256) void to_nhwc(const float* __restrict__ in,
                                               float* __restrict__ out)
{
    __shared__ float tb[32][33];
    const int pix0 = blockIdx.x*32, c0 = blockIdx.y*32, b = blockIdx.z;
    const int tx = threadIdx.x & 31, ty = threadIdx.x >> 5;
    #pragma unroll
    for (int i = 0; i < 4; i++)
        tb[ty + i*8][tx] = in[((size_t)b*256 + c0 + ty + i*8)*4096 + pix0 + tx];
    __syncthreads();
    #pragma unroll
    for (int i = 0; i < 4; i++)
        out[((size_t)b*4096 + pix0 + ty + i*8)*256 + c0 + tx] = tb[tx][ty + i*8];
}

// ---------------- BN stats on NHWC (2-stage, deterministic) -------------------
__global__ __launch_bounds__(256) void bn_stats_h1(const float* __restrict__ src,
                                                   float* __restrict__ part)
{
    const int j = blockIdx.x;           // 128 blocks, 256 pixel-rows each
    float s = 0.f, s2 = 0.f;
    for (int r = 0; r < 256; r++) {
        float v = src[((size_t)j*256 + r)*256 + threadIdx.x];
        s += v; s2 += v*v;
    }
    part[j*256 + threadIdx.x] = s;
    part[32768 + j*256 + threadIdx.x] = s2;
}
__global__ __launch_bounds__(256) void bn_stats_h2(const float* __restrict__ part,
                                                   float* __restrict__ st)
{
    const int c = threadIdx.x;
    float s = 0.f, s2 = 0.f;
    for (int j = 0; j < 128; j++) {
        s  += part[j*256 + c];
        s2 += part[32768 + j*256 + c];
    }
    const float m = s * (1.f/32768.f);
    const float var = s2 * (1.f/32768.f) - m*m;
    st[c] = m;
    st[256 + c] = rsqrtf(var + 1e-5f);
}

__global__ __launch_bounds__(256) void bn_relu_nhwc(float* __restrict__ y,
    const float* __restrict__ st, const float* __restrict__ g, const float* __restrict__ bt)
{
    const int i = blockIdx.x*256 + threadIdx.x;
    const int c = i & 255;
    const float v = (y[i] - st[c]) * st[256 + c] * g[c] + bt[c];
    y[i] = fmaxf(v, 0.f);
}

// ---------------- BN stats on NCHW (d2 / res) ----------------------------------
__global__ __launch_bounds__(256) void bn_stats(const float* __restrict__ src,
                                                float* __restrict__ st)
{
    const int c = blockIdx.x;
    float s = 0.f, s2 = 0.f;
    for (int i = threadIdx.x; i < BN*HWn; i += 256) {
        const int b = i >> 12, pix = i & 4095;
        const float v = src[(((size_t)b*C + c) << 12) + pix];
        s += v; s2 += v*v;
    }
    __shared__ float sh[512];
    sh[threadIdx.x] = s; sh[256 + threadIdx.x] = s2;
    __syncthreads();
    for (int o = 128; o > 0; o >>= 1) {
        if (threadIdx.x < o) {
            sh[threadIdx.x]       += sh[threadIdx.x + o];
            sh[256 + threadIdx.x] += sh[256 + threadIdx.x + o];
        }
        __syncthreads();
    }
    if (threadIdx.x == 0) {
        const float m   = sh[0]   * (1.f/32768.f);
        const float var = sh[256] * (1.f/32768.f) - m*m;
        st[c]       = m;
        st[256 + c] = rsqrtf(var + 1e-5f);
    }
}

// ---------------- deformable gather on NHWC -> col ----------------------------
// block = 1 pixel, 9 warps (one per tap), lane covers 8 channels.
__global__ __launch_bounds__(288) void deform_sample(
    const float* __restrict__ y1h, const float* __restrict__ off,
    const float* __restrict__ msk, float* __restrict__ col)
{
    const int p = threadIdx.x >> 5, lane = threadIdx.x & 31;
    const int pix = blockIdx.x, b = blockIdx.y;
    const int ho = pix >> 6, wo = pix & 63;

    const float dy = off[((size_t)b*18 + 2*p    )*4096 + pix];
    const float dx = off[((size_t)b*18 + 2*p + 1)*4096 + pix];
    const float m  = msk[((size_t)b*9 + p)*4096 + pix];
    const float py = (float)(ho - 1 + p/3) + dy;
    const float px = (float)(wo - 1 + p%3) + dx;

    const float y0f = floorf(py), x0f = floorf(px);
    const float ly = py - y0f, lx = px - x0f;
    const int y0 = (int)y0f, x0 = (int)x0f;
    const int y1 = y0 + 1,  x1 = x0 + 1;
    float w00 = (1.f-ly)*(1.f-lx), w01 = (1.f-ly)*lx, w10 = ly*(1.f-lx), w11 = ly*lx;
    const bool vy0 = (y0 >= 0) && (y0 < 64), vy1 = (y1 >= 0) && (y1 < 64);
    const bool vx0 = (x0 >= 0) && (x0 < 64), vx1 = (x1 >= 0) && (x1 < 64);
    if (!(vy0 && vx0)) w00 = 0.f;
    if (!(vy0 && vx1)) w01 = 0.f;
    if (!(vy1 && vx0)) w10 = 0.f;
    if (!(vy1 && vx1)) w11 = 0.f;
    const int yc0 = min(max(y0, 0), 63), yc1 = min(max(y1, 0), 63);
    const int xc0 = min(max(x0, 0), 63), xc1 = min(max(x1, 0), 63);
    w00 *= m; w01 *= m; w10 *= m; w11 *= m;

    const float* base = y1h + (size_t)b*4096*256;
    const float* p00 = base + (size_t)(yc0*64 + xc0)*256 + lane*8;
    const float* p01 = base + (size_t)(yc0*64 + xc1)*256 + lane*8;
    const float* p10 = base + (size_t)(yc1*64 + xc0)*256 + lane*8;
    const float* p11 = base + (size_t)(yc1*64 + xc1)*256 + lane*8;
    float* cp = col + ((size_t)b*4096 + pix)*KFULL + p*256 + lane*8;

    #pragma unroll
    for (int h = 0; h < 2; h++) {
        const float4 a = *(const float4*)(p00 + h*4);
        const float4 c2 = *(const float4*)(p01 + h*4);
        const float4 d = *(const float4*)(p10 + h*4);
        const float4 e = *(const float4*)(p11 + h*4);
        float4 s;
        s.x = w00*a.x + w01*c2.x + w10*d.x + w11*e.x;
        s.y = w00*a.y + w01*c2.y + w10*d.y + w11*e.y;
        s.z = w00*a.z + w01*c2.z + w10*d.z + w11*e.z;
        s.w = w00*a.w + w01*c2.w + w10*d.w + w11*e.w;
        *(float4*)(cp + h*4) = s;
    }
}

// ---------------- final: relu( bn2(d2) + bn3(res) ) ---------------------------
__global__ __launch_bounds__(256) void final_fuse(
    const float* __restrict__ d2, const float* __restrict__ res,
    const float* __restrict__ st,
    const float* __restrict__ g2, const float* __restrict__ bt2,
    const float* __restrict__ g3, const float* __restrict__ bt3,
    float* __restrict__ out)
{
    const int i = blockIdx.x*256 + threadIdx.x;
    const int c = (i >> 12) & 255;
    const float a = (d2[i]  - st[512 + c])  * st[768 + c]  * g2[c] + bt2[c];
    const float r = (res[i] - st[1024 + c]) * st[1280 + c] * g3[c] + bt3[c];
    out[i] = fmaxf(a + r, 0.f);
}

// ---------------- launcher ------------------------------------------------------
extern "C" void kernel_launch(void* const* d_in, const int* in_sizes, int n_in,
                              void* d_out, int out_size)
{
    const float* x     = (const float*)d_in[0];
    const float* w1    = (const float*)d_in[2];
    const float* b1    = (const float*)d_in[3];
    const float* g1    = (const float*)d_in[4];
    const float* bt1   = (const float*)d_in[5];
    const float* w_off = (const float*)d_in[6];
    const float* b_off = (const float*)d_in[7];
    const float* w_mod = (const float*)d_in[8];
    const float* b_mod = (const float*)d_in[9];
    const float* w_d   = (const float*)d_in[10];
    const float* b_d   = (const float*)d_in[11];
    const float* g2    = (const float*)d_in[12];
    const float* bt2   = (const float*)d_in[13];
    const float* w_ds  = (const float*)d_in[14];
    const float* b_ds  = (const float*)d_in[15];
    const float* g3    = (const float*)d_in[16];
    const float* bt3   = (const float*)d_in[17];

    float *xt, *y1h, *d2, *res, *off, *msk, *col, *st, *w1p, *wdp, *wop, *bp, *part;
    cudaGetSymbolAddress((void**)&xt,   g_xt);
    cudaGetSymbolAddress((void**)&y1h,  g_y1h);
    cudaGetSymbolAddress((void**)&d2,   g_d2);
    cudaGetSymbolAddress((void**)&res,  g_res);
    cudaGetSymbolAddress((void**)&off,  g_off);
    cudaGetSymbolAddress((void**)&msk,  g_mask);
    cudaGetSymbolAddress((void**)&col,  g_col);
    cudaGetSymbolAddress((void**)&st,   g_stats);
    cudaGetSymbolAddress((void**)&w1p,  g_w1p);
    cudaGetSymbolAddress((void**)&wdp,  g_wdp);
    cudaGetSymbolAddress((void**)&wop,  g_wop);
    cudaGetSymbolAddress((void**)&bp,   g_bp);
    cudaGetSymbolAddress((void**)&part, g_part);

    // 0) layout prep
    to_nhwc<<<dim3(128, 8, BN), 256>>>(x, xt);
    permuteK<<<256*KFULL/256, 256>>>(w1,  w1p);
    permuteK<<<256*KFULL/256, 256>>>(w_d, wdp);
    pack_offmod<<<(27*KFULL + 255)/256, 256>>>(w_off, w_mod, b_off, b_mod, wop, bp);

    // 1) conv1 (implicit 3x3 GEMM, NHWC out)
    gemm_v2<true,1><<<dim3(32, 4, BN), 128>>>(w1p, xt, b1, y1h, nullptr, KFULL, 64, 0);
    // 2) BN1 + ReLU (NHWC, in place)
    bn_stats_h1<<<128, 256>>>(y1h, part);
    bn_stats_h2<<<1, 256>>>(part, st);
    bn_relu_nhwc<<<(int)((size_t)BN*HWn*C/256), 256>>>(y1h, st, g1, bt1);
    // 3) offsets + modulation (implicit 3x3 GEMM, 27 rows)
    gemm_v2<true,2><<<dim3(32, 1, BN), 128>>>(wop, y1h, bp, off, msk, KFULL, 27, 0);
    // 4) bilinear gather -> col (k-contiguous rows)
    deform_sample<<<dim3(HWn, BN), 288>>>(y1h, off, msk, col);
    // 5) deformable GEMM (K=2304), NCHW out
    gemm_v2<false,0><<<dim3(32, 4, BN), 128>>>(wdp, col, b_d, d2, nullptr, KFULL, 64, KFULL);
    // 6) 1x1 shortcut (K=256), NCHW out (w_ds is already [co][ci])
    gemm_v2<false,0><<<dim3(32, 4, BN), 128>>>(w_ds, xt, b_ds, res, nullptr, 256, 64, 256);
    // 7) BN2 / BN3 stats
    bn_stats<<<256, 256>>>(d2,  st + 512);
    bn_stats<<<256, 256>>>(res, st + 1024);
    // 8) fused BN2 + BN3 + add + ReLU
    final_fuse<<<BN*C*HWn/256, 256>>>(d2, res, st, g2, bt2, g3, bt3, (float*)d_out);
}

// round 6
// speedup vs baseline: 3.2142x; 3.2142x over previous
#include <cuda_runtime.h>
#include <math.h>
#include <stdint.h>

#define BN 8
#define C 256
#define HWn 4096
#define KFULL 2304

// ---------------- scratch (device globals: allocation-free) ----------------
__device__ float g_xt [(size_t)BN*HWn*C];        // x NHWC, tf32-rounded
__device__ float g_y1 [(size_t)BN*C*HWn];        // conv1 raw NCHW
__device__ float g_y1h[(size_t)BN*HWn*C];        // bn+relu NHWC, tf32-rounded
__device__ float g_d2 [(size_t)BN*C*HWn];        // deform conv raw NCHW
__device__ float g_res[(size_t)BN*C*HWn];        // 1x1 raw NCHW
__device__ float g_off[BN*18*HWn];
__device__ float g_mask[BN*9*HWn];
__device__ float g_col[(size_t)BN*HWn*KFULL];    // [b][pix][k=p*256+ci], rounded
__device__ float g_stats[6*256];
__device__ float g_w1p[256*KFULL];               // w1  -> [co][t*256+ci] rounded
__device__ float g_wdp[256*KFULL];               // w_d -> [co][t*256+ci] rounded
__device__ float g_wop[32*KFULL];                // off+mod packed (27 rows + 5 zero)
__device__ float g_wds[256*256];                 // w_ds rounded
__device__ float g_bp[32];

// ---------------- helpers -----------------------------------------------------
__device__ __forceinline__ unsigned f2tf(float v) {
    unsigned u; asm("cvt.rna.tf32.f32 %0, %1;" : "=r"(u) : "f"(v)); return u;
}
__device__ __forceinline__ float f2tff(float v) {
    return __uint_as_float(f2tf(v));
}
__device__ __forceinline__ uint32_t s2u(const void* p) {
    uint32_t a;
    asm("{ .reg .u64 t; cvta.to.shared.u64 t, %1; cvt.u32.u64 %0, t; }" : "=r"(a) : "l"(p));
    return a;
}
__device__ __forceinline__ void cpa16(uint32_t dst, const void* src, bool v) {
    int sz = v ? 16 : 0;
    asm volatile("cp.async.cg.shared.global [%0], [%1], 16, %2;"
                 :: "r"(dst), "l"(src), "r"(sz) : "memory");
}
__device__ __forceinline__ void mma8(float* d, const uint4& a, const uint2& b) {
    asm volatile("mma.sync.aligned.m16n8k8.row.col.f32.tf32.tf32.f32 "
        "{%0,%1,%2,%3}, {%4,%5,%6,%7}, {%8,%9}, {%0,%1,%2,%3};"
        : "+f"(d[0]), "+f"(d[1]), "+f"(d[2]), "+f"(d[3])
        : "r"(a.x), "r"(a.y), "r"(a.z), "r"(a.w), "r"(b.x), "r"(b.y));
}

// ---------------- unified tf32 GEMM, cp.async double-buffered ------------------
// D[M co x 128 pix] = A[co][k] * B[k][pix], K chunks of 32, 256 threads.
// All inputs PRE-ROUNDED to tf32 (low mantissa bits zero) -> no cvt here.
// CONVB: B = implicit 3x3 im2col of NHWC tensor Bm, k = t*256 + ci.
// else:  B[k][pix] = Bm[(b*4096+pix)*ROWLEN + k]  (k-contiguous rows).
// EPI 0: NCHW out + bias.   EPI 2: rows<18 -> off, rows 18..26 -> 2*sigmoid.
template<int M, bool CONVB, int EPI>
__global__ void __launch_bounds__(256, 2) gemm_v3(
    const float* __restrict__ A, const float* __restrict__ Bm,
    const float* __restrict__ bias,
    float* __restrict__ out0, float* __restrict__ out1,
    int Kdim, int ROWLEN)
{
    constexpr int WN = 256 / M;        // n-warps: 2 (M=128) or 8 (M=32)
    constexpr int NT = M / 16;         // n8-tiles per warp: 8 or 2
    constexpr int APITCH = 36;         // floats, conflict-free & 16B aligned
    constexpr int ABUF = M * APITCH;
    constexpr int BBUF = 128 * APITCH;
    constexpr int STAGE = ABUF + BBUF;

    extern __shared__ float sm[];
    const int tid = threadIdx.x, lane = tid & 31, warp = tid >> 5;
    const int wm = warp / WN, wn = warp % WN;
    const int g = lane >> 2, tig = lane & 3;
    const int pix0 = blockIdx.x * 128, co0 = blockIdx.y * M, b = blockIdx.z;
    const uint32_t smu = s2u(sm);

    float acc[2][NT][4] = {};
    const int nch = Kdim >> 5;

    auto stage = [&](int ic, int buf) {
        const int k0 = ic << 5;
        uint32_t sA = smu + buf * STAGE * 4;
        uint32_t sB = sA + ABUF * 4;
        #pragma unroll
        for (int i = 0; i < M/32; i++) {            // A: M x 32k
            int idx = tid + i*256;
            int row = idx >> 3, kq = idx & 7;
            cpa16(sA + (row*APITCH + kq*4)*4,
                  A + (size_t)(co0+row)*Kdim + k0 + kq*4, true);
        }
        int ty = 0, tx = 0, ci0 = 0;
        if (CONVB) { int t = k0 >> 8; ty = t/3 - 1; tx = t%3 - 1; ci0 = k0 & 255; }
        #pragma unroll
        for (int i = 0; i < 4; i++) {               // B: 32k x 128pix
            int idx = tid + i*256;
            int pp = idx >> 3, kq = idx & 7;
            uint32_t dst = sB + (pp*APITCH + kq*4)*4;
            if (CONVB) {
                int pix = pix0 + pp;
                int py = (pix >> 6) + ty, px = (pix & 63) + tx;
                bool v = (py >= 0) && (py < 64) && (px >= 0) && (px < 64);
                const float* src = Bm + ((size_t)b*4096 + (v ? (py*64+px) : 0))*256
                                 + ci0 + kq*4;
                cpa16(dst, src, v);
            } else {
                cpa16(dst, Bm + ((size_t)b*4096 + pix0 + pp)*(size_t)ROWLEN
                           + k0 + kq*4, true);
            }
        }
        asm volatile("cp.async.commit_group;" ::: "memory");
    };

    stage(0, 0);
    for (int ic = 0; ic < nch; ic++) {
        const int buf = ic & 1;
        if (ic + 1 < nch) {
            stage(ic + 1, buf ^ 1);
            asm volatile("cp.async.wait_group 1;" ::: "memory");
        } else {
            asm volatile("cp.async.wait_group 0;" ::: "memory");
        }
        __syncthreads();
        const float* sA = sm + buf*STAGE;
        const float* sB = sA + ABUF;
        #pragma unroll
        for (int k8 = 0; k8 < 4; k8++) {
            const int kb = k8 * 8;
            uint4 af[2];
            #pragma unroll
            for (int m = 0; m < 2; m++) {
                const int cw = wm*32 + m*16;
                af[m].x = __float_as_uint(sA[(cw+g  )*APITCH + kb+tig  ]);
                af[m].y = __float_as_uint(sA[(cw+g+8)*APITCH + kb+tig  ]);
                af[m].z = __float_as_uint(sA[(cw+g  )*APITCH + kb+tig+4]);
                af[m].w = __float_as_uint(sA[(cw+g+8)*APITCH + kb+tig+4]);
            }
            #pragma unroll
            for (int nn = 0; nn < NT; nn++) {
                const int pc = wn*(NT*8) + nn*8 + g;
                uint2 bb;
                bb.x = __float_as_uint(sB[pc*APITCH + kb+tig  ]);
                bb.y = __float_as_uint(sB[pc*APITCH + kb+tig+4]);
                mma8(acc[0][nn], af[0], bb);
                mma8(acc[1][nn], af[1], bb);
            }
        }
        __syncthreads();
    }

    // ---- epilogue (reuses smem) ----
    float* sE = sm;
    if (EPI == 0) {
        #pragma unroll
        for (int p = 0; p < M/32; p++) {
            if (wm == p) {
                #pragma unroll
                for (int m = 0; m < 2; m++)
                    #pragma unroll
                    for (int nn = 0; nn < NT; nn++) {
                        const int r = m*16 + g;
                        const int pl = wn*(NT*8) + nn*8 + tig*2;
                        sE[r*132 + pl]       = acc[m][nn][0];
                        sE[r*132 + pl+1]     = acc[m][nn][1];
                        sE[(r+8)*132 + pl]   = acc[m][nn][2];
                        sE[(r+8)*132 + pl+1] = acc[m][nn][3];
                    }
            }
            __syncthreads();
            #pragma unroll
            for (int i = 0; i < 4; i++) {
                int idx = tid + i*256;
                int r = idx >> 5, p4 = idx & 31;
                float4 v = *(float4*)&sE[r*132 + p4*4];
                int co = co0 + p*32 + r;
                float bb = bias[co];
                v.x += bb; v.y += bb; v.z += bb; v.w += bb;
                *(float4*)(out0 + (((size_t)b*256 + co) << 12) + pix0 + p4*4) = v;
            }
            __syncthreads();
        }
    } else {   // EPI 2: offsets + mask (M=32, all warps wm==0)
        #pragma unroll
        for (int m = 0; m < 2; m++)
            #pragma unroll
            for (int nn = 0; nn < NT; nn++) {
                const int r = m*16 + g;
                const int pl = wn*(NT*8) + nn*8 + tig*2;
                sE[r*132 + pl]       = acc[m][nn][0];
                sE[r*132 + pl+1]     = acc[m][nn][1];
                sE[(r+8)*132 + pl]   = acc[m][nn][2];
                sE[(r+8)*132 + pl+1] = acc[m][nn][3];
            }
        __syncthreads();
        if (tid < 128) {
            const int pix = pix0 + tid;
            #pragma unroll
            for (int r = 0; r < 27; r++) {
                float v = sE[r*132 + tid] + bias[r];
                if (r < 18) out0[((size_t)b*18 + r)*4096 + pix] = v;
                else        out1[((size_t)b*9 + r - 18)*4096 + pix] = 2.f/(1.f + expf(-v));
            }
        }
    }
}

// ---------------- prep kernels -------------------------------------------------
__global__ __launch_bounds__(256) void permuteK_round(const float* __restrict__ in,
                                                      float* __restrict__ out)
{
    int i = blockIdx.x*256 + threadIdx.x;
    int co = i / KFULL, r = i - co*KFULL;
    int t = r >> 8, ci = r & 255;
    out[i] = f2tff(in[co*KFULL + ci*9 + t]);
}

__global__ __launch_bounds__(256) void pack_offmod_round(
    const float* __restrict__ w_off, const float* __restrict__ w_mod,
    const float* __restrict__ b_off, const float* __restrict__ b_mod,
    float* __restrict__ wp, float* __restrict__ bp)
{
    int i = blockIdx.x*256 + threadIdx.x;
    if (i < 32*KFULL) {
        int o = i / KFULL, r = i - o*KFULL;
        int t = r >> 8, ci = r & 255;
        float v = 0.f;
        if (o < 18)      v = w_off[o*KFULL + ci*9 + t];
        else if (o < 27) v = w_mod[(o-18)*KFULL + ci*9 + t];
        wp[i] = f2tff(v);
    }
    if (i < 27) bp[i] = (i < 18) ? b_off[i] : b_mod[i-18];
}

__global__ __launch_bounds__(256) void round_wds(const float* __restrict__ in,
                                                 float* __restrict__ out)
{
    int i = blockIdx.x*256 + threadIdx.x;
    out[i] = f2tff(in[i]);
}

// NCHW -> NHWC (rounded), optional BN+ReLU (st==nullptr: plain round)
__global__ __launch_bounds__(256) void nhwc_round(const float* __restrict__ in,
    float* __restrict__ out, const float* __restrict__ st,
    const float* __restrict__ g, const float* __restrict__ bt)
{
    __shared__ float tb[32][33];
    const int pix0 = blockIdx.x*32, c0 = blockIdx.y*32, b = blockIdx.z;
    const int tx = threadIdx.x & 31, ty = threadIdx.x >> 5;
    #pragma unroll
    for (int i = 0; i < 4; i++) {
        const int c = c0 + ty + i*8;
        float v = in[((size_t)b*256 + c)*4096 + pix0 + tx];
        if (st) {
            v = (v - st[c]) * st[256 + c] * g[c] + bt[c];
            v = fmaxf(v, 0.f);
        }
        tb[ty + i*8][tx] = f2tff(v);
    }
    __syncthreads();
    #pragma unroll
    for (int i = 0; i < 4; i++)
        out[((size_t)b*4096 + pix0 + ty + i*8)*256 + c0 + tx] = tb[tx][ty + i*8];
}

// ---------------- BN stats on NCHW ----------------------------------------------
__global__ __launch_bounds__(256) void bn_stats(const float* __restrict__ src,
                                                float* __restrict__ st)
{
    const int c = blockIdx.x;
    float s = 0.f, s2 = 0.f;
    for (int i = threadIdx.x; i < BN*HWn; i += 256) {
        const int b = i >> 12, pix = i & 4095;
        const float v = src[(((size_t)b*C + c) << 12) + pix];
        s += v; s2 += v*v;
    }
    __shared__ float sh[512];
    sh[threadIdx.x] = s; sh[256 + threadIdx.x] = s2;
    __syncthreads();
    for (int o = 128; o > 0; o >>= 1) {
        if (threadIdx.x < o) {
            sh[threadIdx.x]       += sh[threadIdx.x + o];
            sh[256 + threadIdx.x] += sh[256 + threadIdx.x + o];
        }
        __syncthreads();
    }
    if (threadIdx.x == 0) {
        const float m   = sh[0]   * (1.f/32768.f);
        const float var = sh[256] * (1.f/32768.f) - m*m;
        st[c]       = m;
        st[256 + c] = rsqrtf(var + 1e-5f);
    }
}

// ---------------- deformable gather on NHWC -> col [b][pix][k] ------------------
__global__ __launch_bounds__(288) void deform_sample(
    const float* __restrict__ y1h, const float* __restrict__ off,
    const float* __restrict__ msk, float* __restrict__ col)
{
    const int p = threadIdx.x >> 5, lane = threadIdx.x & 31;
    const int pix = blockIdx.x, b = blockIdx.y;
    const int ho = pix >> 6, wo = pix & 63;

    const float dy = off[((size_t)b*18 + 2*p    )*4096 + pix];
    const float dx = off[((size_t)b*18 + 2*p + 1)*4096 + pix];
    const float m  = msk[((size_t)b*9 + p)*4096 + pix];
    const float py = (float)(ho - 1 + p/3) + dy;
    const float px = (float)(wo - 1 + p%3) + dx;

    const float y0f = floorf(py), x0f = floorf(px);
    const float ly = py - y0f, lx = px - x0f;
    const int y0 = (int)y0f, x0 = (int)x0f;
    const int y1 = y0 + 1,  x1 = x0 + 1;
    float w00 = (1.f-ly)*(1.f-lx), w01 = (1.f-ly)*lx, w10 = ly*(1.f-lx), w11 = ly*lx;
    const bool vy0 = (y0 >= 0) && (y0 < 64), vy1 = (y1 >= 0) && (y1 < 64);
    const bool vx0 = (x0 >= 0) && (x0 < 64), vx1 = (x1 >= 0) && (x1 < 64);
    if (!(vy0 && vx0)) w00 = 0.f;
    if (!(vy0 && vx1)) w01 = 0.f;
    if (!(vy1 && vx0)) w10 = 0.f;
    if (!(vy1 && vx1)) w11 = 0.f;
    const int yc0 = min(max(y0, 0), 63), yc1 = min(max(y1, 0), 63);
    const int xc0 = min(max(x0, 0), 63), xc1 = min(max(x1, 0), 63);
    w00 *= m; w01 *= m; w10 *= m; w11 *= m;

    const float* base = y1h + (size_t)b*4096*256;
    const float* p00 = base + (size_t)(yc0*64 + xc0)*256 + lane*8;
    const float* p01 = base + (size_t)(yc0*64 + xc1)*256 + lane*8;
    const float* p10 = base + (size_t)(yc1*64 + xc0)*256 + lane*8;
    const float* p11 = base + (size_t)(yc1*64 + xc1)*256 + lane*8;
    float* cp = col + ((size_t)b*4096 + pix)*KFULL + p*256 + lane*8;

    #pragma unroll
    for (int h = 0; h < 2; h++) {
        const float4 a = *(const float4*)(p00 + h*4);
        const float4 c2 = *(const float4*)(p01 + h*4);
        const float4 d = *(const float4*)(p10 + h*4);
        const float4 e = *(const float4*)(p11 + h*4);
        float4 s;
        s.x = f2tff(w00*a.x + w01*c2.x + w10*d.x + w11*e.x);
        s.y = f2tff(w00*a.y + w01*c2.y + w10*d.y + w11*e.y);
        s.z = f2tff(w00*a.z + w01*c2.z + w10*d.z + w11*e.z);
        s.w = f2tff(w00*a.w + w01*c2.w + w10*d.w + w11*e.w);
        *(float4*)(cp + h*4) = s;
    }
}

// ---------------- final: relu( bn2(d2) + bn3(res) ) -----------------------------
__global__ __launch_bounds__(256) void final_fuse(
    const float* __restrict__ d2, const float* __restrict__ res,
    const float* __restrict__ st,
    const float* __restrict__ g2, const float* __restrict__ bt2,
    const float* __restrict__ g3, const float* __restrict__ bt3,
    float* __restrict__ out)
{
    const int i = blockIdx.x*256 + threadIdx.x;
    const int c = (i >> 12) & 255;
    const float a = (d2[i]  - st[512 + c])  * st[768 + c]  * g2[c] + bt2[c];
    const float r = (res[i] - st[1024 + c]) * st[1280 + c] * g3[c] + bt3[c];
    out[i] = fmaxf(a + r, 0.f);
}

// ---------------- launcher -------------------------------------------------------
extern "C" void kernel_launch(void* const* d_in, const int* in_sizes, int n_in,
                              void* d_out, int out_size)
{
    const float* x     = (const float*)d_in[0];
    const float* w1    = (const float*)d_in[2];
    const float* b1    = (const float*)d_in[3];
    const float* g1    = (const float*)d_in[4];
    const float* bt1   = (const float*)d_in[5];
    const float* w_off = (const float*)d_in[6];
    const float* b_off = (const float*)d_in[7];
    const float* w_mod = (const float*)d_in[8];
    const float* b_mod = (const float*)d_in[9];
    const float* w_d   = (const float*)d_in[10];
    const float* b_d   = (const float*)d_in[11];
    const float* g2    = (const float*)d_in[12];
    const float* bt2   = (const float*)d_in[13];
    const float* w_ds  = (const float*)d_in[14];
    const float* b_ds  = (const float*)d_in[15];
    const float* g3    = (const float*)d_in[16];
    const float* bt3   = (const float*)d_in[17];

    float *xt, *y1, *y1h, *d2, *res, *off, *msk, *col, *st, *w1p, *wdp, *wop, *wds, *bp;
    cudaGetSymbolAddress((void**)&xt,  g_xt);
    cudaGetSymbolAddress((void**)&y1,  g_y1);
    cudaGetSymbolAddress((void**)&y1h, g_y1h);
    cudaGetSymbolAddress((void**)&d2,  g_d2);
    cudaGetSymbolAddress((void**)&res, g_res);
    cudaGetSymbolAddress((void**)&off, g_off);
    cudaGetSymbolAddress((void**)&msk, g_mask);
    cudaGetSymbolAddress((void**)&col, g_col);
    cudaGetSymbolAddress((void**)&st,  g_stats);
    cudaGetSymbolAddress((void**)&w1p, g_w1p);
    cudaGetSymbolAddress((void**)&wdp, g_wdp);
    cudaGetSymbolAddress((void**)&wop, g_wop);
    cudaGetSymbolAddress((void**)&wds, g_wds);
    cudaGetSymbolAddress((void**)&bp,  g_bp);

    const int SM128 = 2 * (128*36 + 128*36) * 4;   // 73728
    const int SM32  = 2 * (32*36  + 128*36) * 4;   // 46080
    cudaFuncSetAttribute(gemm_v3<128,true,0>,  cudaFuncAttributeMaxDynamicSharedMemorySize, SM128);
    cudaFuncSetAttribute(gemm_v3<128,false,0>, cudaFuncAttributeMaxDynamicSharedMemorySize, SM128);
    cudaFuncSetAttribute(gemm_v3<32,true,2>,   cudaFuncAttributeMaxDynamicSharedMemorySize, SM32);

    // 0) prep: NHWC rounded x, permuted+rounded weights
    nhwc_round<<<dim3(128, 8, BN), 256>>>(x, xt, nullptr, nullptr, nullptr);
    permuteK_round<<<256*KFULL/256, 256>>>(w1,  w1p);
    permuteK_round<<<256*KFULL/256, 256>>>(w_d, wdp);
    pack_offmod_round<<<32*KFULL/256, 256>>>(w_off, w_mod, b_off, b_mod, wop, bp);
    round_wds<<<256*256/256, 256>>>(w_ds, wds);

    // 1) conv1: implicit 3x3 GEMM (B from NHWC x) -> y1 NCHW
    gemm_v3<128,true,0><<<dim3(32, 2, BN), 256, SM128>>>(w1p, xt, b1, y1, nullptr, KFULL, 0);
    // 2) BN1 stats + fused BN+ReLU+round+transpose -> y1h NHWC
    bn_stats<<<256, 256>>>(y1, st);
    nhwc_round<<<dim3(128, 8, BN), 256>>>(y1, y1h, st, g1, bt1);
    // 3) offsets + modulation: implicit 3x3 GEMM over y1h, 27 rows (padded to 32)
    gemm_v3<32,true,2><<<dim3(32, 1, BN), 256, SM32>>>(wop, y1h, bp, off, msk, KFULL, 0);
    // 4) bilinear gather -> col [b][pix][k] (rounded)
    deform_sample<<<dim3(HWn, BN), 288>>>(y1h, off, msk, col);
    // 5) deformable GEMM (K=2304) -> d2 NCHW
    gemm_v3<128,false,0><<<dim3(32, 2, BN), 256, SM128>>>(wdp, col, b_d, d2, nullptr, KFULL, KFULL);
    // 6) 1x1 shortcut (K=256, B from NHWC x) -> res NCHW
    gemm_v3<128,false,0><<<dim3(32, 2, BN), 256, SM128>>>(wds, xt, b_ds, res, nullptr, 256, 256);
    // 7) BN2 / BN3 stats
    bn_stats<<<256, 256>>>(d2,  st + 512);
    bn_stats<<<256, 256>>>(res, st + 1024);
    // 8) fused BN2 + BN3 + add + ReLU
    final_fuse<<<BN*C*HWn/256, 256>>>(d2, res, st, g2, bt2, g3, bt3, (float*)d_out);
}